// round 1
// baseline (speedup 1.0000x reference)
#include <cuda_runtime.h>
#include <cstdint>
#include <cstddef>

// Problem constants
#define B_      64
#define S_      784
#define T_      500
#define N_      512
#define TP_     522      // conv output length: 500 + 2*21 - 21 + 1
#define KS_     21
#define THETA_  40
#define CAP_    128      // max spikes per (b,tau); mean ~39, sd ~6 -> 128 is +14 sigma
#define NT_     32       // neurons per CTA
#define TC_     64       // tau chunk size
#define THREADS_ 512

// Scratch (static __device__ arrays: allocation-free per harness rules)
__device__ int            g_cnt[B_ * T_];
__device__ unsigned short g_list[B_ * T_ * CAP_];            // [b][tau][c] -> s
__device__ int            g_pot[(size_t)B_ * TP_ * N_];      // [b][t][n]
__device__ int            g_max[B_ * TP_];
__device__ int            g_arg[B_ * TP_];

__device__ __forceinline__ int dp4a_(unsigned a, unsigned b, int c) {
    int r;
    asm("dp4a.u32.u32 %0, %1, %2, %3;" : "=r"(r) : "r"(a), "r"(b), "r"(c));
    return r;
}

// ---------------------------------------------------------------------------
__global__ void zero_cnt_kernel() {
    int i = blockIdx.x * blockDim.x + threadIdx.x;
    if (i < B_ * T_) g_cnt[i] = 0;
}

// Build per-(b,tau) compact spike lists from dense fp32 spikes.
__global__ void prepass_kernel(const float4* __restrict__ x) {
    const int T4 = T_ / 4;             // 125
    int idx = blockIdx.x * blockDim.x + threadIdx.x;
    if (idx >= B_ * S_ * T4) return;
    float4 v = x[idx];
    int t4 = idx % T4;
    int bs = idx / T4;
    int s  = bs % S_;
    int b  = bs / S_;
    int tb = t4 * 4;
    float a0 = v.x, a1 = v.y, a2 = v.z, a3 = v.w;
    if (a0 != 0.0f) { int c = atomicAdd(&g_cnt[b * T_ + tb + 0], 1); if (c < CAP_) g_list[(b * T_ + tb + 0) * CAP_ + c] = (unsigned short)s; }
    if (a1 != 0.0f) { int c = atomicAdd(&g_cnt[b * T_ + tb + 1], 1); if (c < CAP_) g_list[(b * T_ + tb + 1) * CAP_ + c] = (unsigned short)s; }
    if (a2 != 0.0f) { int c = atomicAdd(&g_cnt[b * T_ + tb + 2], 1); if (c < CAP_) g_list[(b * T_ + tb + 2) * CAP_ + c] = (unsigned short)s; }
    if (a3 != 0.0f) { int c = atomicAdd(&g_cnt[b * T_ + tb + 3], 1); if (c < CAP_) g_list[(b * T_ + tb + 3) * CAP_ + c] = (unsigned short)s; }
}

// ---------------------------------------------------------------------------
// Main potential kernel. CTA = (neuron tile of 32, batch b).
// smem layout (bytes):
#define OFF_W    0                    // u8 [S_][NT_] transposed weights      25088
#define OFF_POT  25088                // i32 [NT_][TP_] accumulators          66816
#define OFF_ZLO  91904                // u32 [NT_][TC_+1]                      8320
#define OFF_ZHI  100224               // u32 [NT_][TC_+1]                      8320
#define OFF_CNT  108544               // i32 [T_]                              2000
#define OFF_TL   110544               // u32 [KS_]                               84
#define OFF_TH   110628               // u32 [KS_]                               84
#define SMEM_TOTAL 110712

__global__ void __launch_bounds__(THREADS_) pot_kernel(const int* __restrict__ weight,
                                                       const int* __restrict__ table) {
    extern __shared__ unsigned char smem[];
    unsigned char* w_smT = smem + OFF_W;
    int*       pot_sm = (int*)(smem + OFF_POT);
    unsigned*  zlo    = (unsigned*)(smem + OFF_ZLO);
    unsigned*  zhi    = (unsigned*)(smem + OFF_ZHI);
    int*       cnt_sm = (int*)(smem + OFF_CNT);
    unsigned*  TLs    = (unsigned*)(smem + OFF_TL);
    unsigned*  THs    = (unsigned*)(smem + OFF_TH);

    const int b   = blockIdx.y;
    const int n0  = blockIdx.x * NT_;
    const int tid = threadIdx.x;

    // Load weight tile transposed: w_smT[s*NT_ + r] = weight[(n0+r)*S_ + s]
    for (int i = tid; i < NT_ * S_; i += THREADS_) {
        int r = i / S_;
        int s = i - r * S_;
        w_smT[s * NT_ + r] = (unsigned char)weight[(n0 + r) * S_ + s];
    }
    // Response table: input is time-flipped -> orig[v][j] = table[v][KS_-1-j].
    // Pack per-j byte columns: TLs[j] = orig[0..3][j], THs[j] = orig[4..7][j].
    if (tid < KS_) {
        int j = tid;
        unsigned lo = 0, hi = 0;
#pragma unroll
        for (int v = 0; v < 4; v++) lo |= ((unsigned)table[v * KS_ + (KS_ - 1 - j)]) << (8 * v);
#pragma unroll
        for (int v = 4; v < 8; v++) hi |= ((unsigned)table[v * KS_ + (KS_ - 1 - j)]) << (8 * (v - 4));
        TLs[j] = lo; THs[j] = hi;
    }
    for (int i = tid; i < T_; i += THREADS_) {
        int c = g_cnt[b * T_ + i];
        cnt_sm[i] = c < CAP_ ? c : CAP_;
    }
    for (int i = tid; i < NT_ * TP_; i += THREADS_) pot_sm[i] = 0;
    __syncthreads();

    const int warpid = tid >> 5, lane = tid & 31;
    const int tl = tid & 15, n2 = tid >> 4;

    for (int c0 = 0; c0 < T_; c0 += TC_) {
        const int tauEnd = (c0 + TC_ < T_) ? (c0 + TC_) : T_;

        // Phase 1: packed weight-histogram z[v] per (n=lane, tau). Warp covers
        // 32 neurons for one tau: spike index s is warp-uniform (broadcast),
        // w_smT read is 4-lane word-broadcast, conflict-free.
#pragma unroll
        for (int q = 0; q < TC_ / 16; q++) {
            int tau = c0 + warpid * (TC_ / 16) + q;
            if (tau < tauEnd) {
                int cnt = cnt_sm[tau];
                const unsigned short* lp = &g_list[(b * T_ + tau) * CAP_];
                unsigned long long z = 0ull;
#pragma unroll 4
                for (int c = 0; c < cnt; c++) {
                    int s = lp[c];                       // uniform across warp
                    int v = w_smT[s * NT_ + lane];
                    z += 1ull << (v << 3);
                }
                int ti = tau - c0;
                zlo[lane * (TC_ + 1) + ti] = (unsigned)z;
                zhi[lane * (TC_ + 1) + ti] = (unsigned)(z >> 32);
            }
        }
        __syncthreads();

        // Phase 2: gather pot[n][t] += sum_j dp4a(z[tau], tab[j]) for tau in chunk.
        // Each (n,t) owned by exactly one thread -> no atomics.
#pragma unroll
        for (int k = 0; k < 6; k++) {
            int t = c0 + 1 + tl + (k << 4);
            if (t <= tauEnd + (KS_ - 1)) {
                int jlo = t - tauEnd;       if (jlo < 0) jlo = 0;
                int jhi = t - 1 - c0;       if (jhi > KS_ - 1) jhi = KS_ - 1;
                int acc = 0;
                for (int j = jlo; j <= jhi; j++) {
                    int ti = t - 1 - j - c0;
                    acc = dp4a_(zlo[n2 * (TC_ + 1) + ti], TLs[j], acc);
                    acc = dp4a_(zhi[n2 * (TC_ + 1) + ti], THs[j], acc);
                }
                pot_sm[n2 * TP_ + t] += acc;
            }
        }
        __syncthreads();
    }

    // Writeout pot -> global [b][t][n] (n fastest => coalesced)
    for (int i = tid; i < NT_ * TP_; i += THREADS_) {
        int nn = i & (NT_ - 1);
        int t  = i >> 5;
        g_pot[((size_t)b * TP_ + t) * N_ + n0 + nn] = pot_sm[nn * TP_ + t];
    }
}

// ---------------------------------------------------------------------------
// One warp per (b,t): max + first-argmax over 512 neurons.
__global__ void __launch_bounds__(256) reduce_kernel() {
    int gw   = (blockIdx.x * blockDim.x + threadIdx.x) >> 5;   // grid sized exactly
    int lane = threadIdx.x & 31;
    if (gw >= B_ * TP_) return;
    const int* row = g_pot + (size_t)gw * N_;
    int bv = -1, bn = 0;
#pragma unroll
    for (int k = 0; k < N_ / 32; k++) {
        int n = lane + k * 32;           // ascending n per lane: strict > keeps first max
        int v = row[n];
        if (v > bv) { bv = v; bn = n; }
    }
#pragma unroll
    for (int off = 16; off; off >>= 1) {
        int ov = __shfl_down_sync(0xffffffffu, bv, off);
        int on = __shfl_down_sync(0xffffffffu, bn, off);
        if (ov > bv || (ov == bv && on < bn)) { bv = ov; bn = on; }
    }
    if (lane == 0) { g_max[gw] = bv; g_arg[gw] = bn; }
}

// Sequential depression scan: one block per batch, serial part is thread 0.
__global__ void scan_kernel(float* __restrict__ out) {
    __shared__ int smax[TP_];
    __shared__ int sarg[TP_];
    int b = blockIdx.x;
    for (int i = threadIdx.x; i < TP_; i += blockDim.x) {
        smax[i] = g_max[b * TP_ + i];
        sarg[i] = g_arg[b * TP_ + i];
    }
    __syncthreads();
    if (threadIdx.x == 0) {
        int dep = 0;
        for (int t = 0; t < TP_; t++) {
            if (dep == 0 && smax[t] > THETA_) {
                out[((size_t)b * N_ + sarg[t]) * TP_ + t] = 1.0f;
                dep = KS_;                 // 0 + (FODEP+1) - 1 = 21
            } else {
                dep = dep > 0 ? dep - 1 : 0;
            }
        }
    }
}

// ---------------------------------------------------------------------------
extern "C" void kernel_launch(void* const* d_in, const int* in_sizes, int n_in,
                              void* d_out, int out_size) {
    const float* x      = (const float*)d_in[0];   // [64,1,784,500] fp32
    const int*   weight = (const int*)d_in[1];     // [512,784] int32 in [0,8)
    const int*   table  = (const int*)d_in[2];     // [8,21] int32 (flipped)
    float*       out    = (float*)d_out;           // [64,1,512,522] fp32

    cudaFuncSetAttribute(pot_kernel, cudaFuncAttributeMaxDynamicSharedMemorySize, SMEM_TOTAL);

    cudaMemsetAsync(out, 0, (size_t)out_size * sizeof(float), 0);
    zero_cnt_kernel<<<(B_ * T_ + 255) / 256, 256>>>();

    prepass_kernel<<<(B_ * S_ * (T_ / 4) + 255) / 256, 256>>>((const float4*)x);

    dim3 grid(N_ / NT_, B_);
    pot_kernel<<<grid, THREADS_, SMEM_TOTAL>>>(weight, table);

    reduce_kernel<<<(B_ * TP_ * 32) / 256, 256>>>();   // 4176 blocks, exact
    scan_kernel<<<B_, 128>>>(out);
}

// round 2
// speedup vs baseline: 1.4803x; 1.4803x over previous
#include <cuda_runtime.h>
#include <cstdint>
#include <cstddef>

// Problem constants
#define B_      64
#define S_      784
#define T_      500
#define N_      512
#define TP_     522      // conv output length
#define KS_     21
#define THETA_  40
#define CAP_    128      // max spikes per (b,tau); mean ~39, sd ~6
#define NT_     32       // neurons per CTA
#define TC_     64       // tau chunk size
#define THREADS_ 512
#define PSTR_   524      // pot_sm row stride (u16 units)

// Scratch (static __device__ arrays: allocation-free per harness rules)
__device__ int            g_cnt[B_ * T_];
__device__ unsigned short g_list[B_ * T_ * CAP_];   // [b][tau][c] -> s
__device__ unsigned       g_key[B_ * TP_];          // packed (maxv<<10)|(511-n)

__device__ __forceinline__ int dp4a_(unsigned a, unsigned b, int c) {
    int r;
    asm("dp4a.u32.u32 %0, %1, %2, %3;" : "=r"(r) : "r"(a), "r"(b), "r"(c));
    return r;
}

// ---------------------------------------------------------------------------
__global__ void init_kernel() {
    int i = blockIdx.x * blockDim.x + threadIdx.x;
    if (i < B_ * T_)  g_cnt[i] = 0;
    if (i < B_ * TP_) g_key[i] = 0u;
}

// Build per-(b,tau) compact spike lists from dense fp32 spikes.
__global__ void prepass_kernel(const float4* __restrict__ x) {
    const int T4 = T_ / 4;             // 125
    int idx = blockIdx.x * blockDim.x + threadIdx.x;
    if (idx >= B_ * S_ * T4) return;
    float4 v = x[idx];
    int t4 = idx % T4;
    int bs = idx / T4;
    int s  = bs % S_;
    int b  = bs / S_;
    int tb = t4 * 4;
    if (v.x != 0.0f) { int c = atomicAdd(&g_cnt[b * T_ + tb + 0], 1); if (c < CAP_) g_list[(b * T_ + tb + 0) * CAP_ + c] = (unsigned short)s; }
    if (v.y != 0.0f) { int c = atomicAdd(&g_cnt[b * T_ + tb + 1], 1); if (c < CAP_) g_list[(b * T_ + tb + 1) * CAP_ + c] = (unsigned short)s; }
    if (v.z != 0.0f) { int c = atomicAdd(&g_cnt[b * T_ + tb + 2], 1); if (c < CAP_) g_list[(b * T_ + tb + 2) * CAP_ + c] = (unsigned short)s; }
    if (v.w != 0.0f) { int c = atomicAdd(&g_cnt[b * T_ + tb + 3], 1); if (c < CAP_) g_list[(b * T_ + tb + 3) * CAP_ + c] = (unsigned short)s; }
}

// ---------------------------------------------------------------------------
// smem layout (bytes)
#define OFF_W    0                      // u8 [S_][NT_] pre-shifted weights (v<<2)  25088
#define OFF_POT  25088                  // u16 [NT_][PSTR_]                         33536
#define OFF_ZLO  58624                  // u32 [NT_][TC_+1]                          8320
#define OFF_ZHI  66944                  // u32 [NT_][TC_+1]                          8320
#define OFF_CNT  75264                  // i32 [T_]                                  2000
#define OFF_TL   77264                  // u32 [KS_]                                   84
#define OFF_TH   77348                  // u32 [KS_]                                   84
#define SMEM_TOTAL 77440

__global__ void __launch_bounds__(THREADS_) pot_kernel(const int* __restrict__ weight,
                                                       const int* __restrict__ table) {
    extern __shared__ unsigned char smem[];
    unsigned char*  w_smT  = smem + OFF_W;
    unsigned short* pot_sm = (unsigned short*)(smem + OFF_POT);
    unsigned*       zlo    = (unsigned*)(smem + OFF_ZLO);
    unsigned*       zhi    = (unsigned*)(smem + OFF_ZHI);
    int*            cnt_sm = (int*)(smem + OFF_CNT);
    unsigned*       TLs    = (unsigned*)(smem + OFF_TL);
    unsigned*       THs    = (unsigned*)(smem + OFF_TH);

    const int b   = blockIdx.y;
    const int n0  = blockIdx.x * NT_;
    const int tid = threadIdx.x;

    // Weight tile, transposed + pre-shifted: w_smT[s*32 + r] = w[n0+r][s] << 2
    for (int i = tid; i < NT_ * S_; i += THREADS_) {
        int r = i / S_;
        int s = i - r * S_;
        w_smT[s * NT_ + r] = (unsigned char)(weight[(n0 + r) * S_ + s] << 2);
    }
    // Table (input is time-flipped): orig[v][j] = table[v][KS_-1-j]; pack per-j byte columns.
    if (tid < KS_) {
        int j = tid;
        unsigned lo = 0, hi = 0;
#pragma unroll
        for (int v = 0; v < 4; v++) lo |= ((unsigned)table[v * KS_ + (KS_ - 1 - j)]) << (8 * v);
#pragma unroll
        for (int v = 4; v < 8; v++) hi |= ((unsigned)table[v * KS_ + (KS_ - 1 - j)]) << (8 * (v - 4));
        TLs[j] = lo; THs[j] = hi;
    }
    for (int i = tid; i < T_; i += THREADS_) {
        int c = g_cnt[b * T_ + i];
        cnt_sm[i] = c < CAP_ ? c : CAP_;
    }
    for (int i = tid; i < NT_ * PSTR_; i += THREADS_) pot_sm[i] = 0;
    __syncthreads();

    const int warpid = tid >> 5, lane = tid & 31;
    const int tl = tid & 15, n2 = tid >> 4;
    const int tb_off = 1 + 6 * tl;                       // t base offset within chunk

    for (int c0 = 0; c0 < T_; c0 += TC_) {
        const int tauEnd = (c0 + TC_ < T_) ? (c0 + TC_) : T_;
        const int TCcur  = tauEnd - c0;

        // ---- Phase 1: nibble-packed weight histograms, expanded to byte pairs.
        // Warp handles 4 taus; lane = neuron. Spike index uniform across warp.
#pragma unroll
        for (int q = 0; q < 4; q++) {
            int ti = warpid * 4 + q;
            if (ti < TCcur) {
                int tau = c0 + ti;
                int cnt = cnt_sm[tau];
                const unsigned short* lp = &g_list[(b * T_ + tau) * CAP_];
                unsigned zL = 0u, zH = 0u;
                for (int cb = 0; cb < cnt; cb += 15) {
                    int lim = cnt - cb;
                    unsigned z32 = 0u;
#pragma unroll
                    for (int i = 0; i < 15; i++) {
                        if (i < lim) {
                            int s  = __ldg(&lp[cb + i]);            // warp-uniform
                            int sh = w_smT[s * NT_ + lane];         // v<<2, pre-shifted
                            z32 += 1u << sh;
                        }
                    }
                    unsigned a  = z32 & 0x0F0F0F0Fu;
                    unsigned bb = (z32 >> 4) & 0x0F0F0F0Fu;
                    zL += __byte_perm(a, bb, 0x5140);               // counts v0..v3
                    zH += __byte_perm(a, bb, 0x7362);               // counts v4..v7
                }
                zlo[lane * (TC_ + 1) + ti] = zL;
                zhi[lane * (TC_ + 1) + ti] = zH;
            }
        }
        __syncthreads();

        // ---- Phase 2: 6-wide t-block stencil. Thread owns (n2, t in [tb,tb+5]).
        // t = tb+k, tau = tb+4-q  =>  j = t-1-tau = k+q-5 (compile-time per (q,k)).
        {
            const unsigned* zLrow = &zlo[n2 * (TC_ + 1)];
            const unsigned* zHrow = &zhi[n2 * (TC_ + 1)];
            int acc[6] = {0, 0, 0, 0, 0, 0};
#pragma unroll
            for (int q = 0; q < 26; q++) {
                int ti = 6 * tl + 5 - q;                 // tau - c0
                bool ok = (ti >= 0) && (ti < TCcur);
                unsigned zl = ok ? zLrow[ti] : 0u;
                unsigned zh = ok ? zHrow[ti] : 0u;
#pragma unroll
                for (int k = 0; k < 6; k++) {
                    int j = k + q - 5;
                    if (j >= 0 && j <= 20) {
                        acc[k] = dp4a_(zl, TLs[j], acc[k]);
                        acc[k] = dp4a_(zh, THs[j], acc[k]);
                    }
                }
            }
#pragma unroll
            for (int k = 0; k < 6; k++) {
                int t = c0 + tb_off + k;
                if (t < TP_ && acc[k] != 0)
                    pot_sm[n2 * PSTR_ + t] = (unsigned short)(pot_sm[n2 * PSTR_ + t] + acc[k]);
            }
        }
        __syncthreads();
    }

    // ---- Fused per-(b,t) max/argmax over this CTA's 32 neurons -> global atomicMax.
    for (int t = tid; t < TP_; t += THREADS_) {
        int bv = -1, bn = 0;
#pragma unroll
        for (int nn = 0; nn < NT_; nn++) {
            int v = pot_sm[nn * PSTR_ + t];
            if (v > bv) { bv = v; bn = nn; }             // strict > keeps first (smallest nn)
        }
        unsigned key = ((unsigned)bv << 10) | (unsigned)(511 - (n0 + bn));
        atomicMax(&g_key[b * TP_ + t], key);
    }
}

// ---------------------------------------------------------------------------
// Sequential depression scan: one block per batch, serial part on thread 0.
__global__ void scan_kernel(float* __restrict__ out) {
    __shared__ unsigned skey[TP_];
    int b = blockIdx.x;
    for (int i = threadIdx.x; i < TP_; i += blockDim.x)
        skey[i] = g_key[b * TP_ + i];
    __syncthreads();
    if (threadIdx.x == 0) {
        int dep = 0;
        for (int t = 0; t < TP_; t++) {
            int maxv = (int)(skey[t] >> 10);
            if (dep == 0 && maxv > THETA_) {
                int n = 511 - (int)(skey[t] & 1023u);
                out[((size_t)b * N_ + n) * TP_ + t] = 1.0f;
                dep = KS_;                               // (FODEP+1) - 1
            } else {
                dep = dep > 0 ? dep - 1 : 0;
            }
        }
    }
}

// ---------------------------------------------------------------------------
extern "C" void kernel_launch(void* const* d_in, const int* in_sizes, int n_in,
                              void* d_out, int out_size) {
    const float* x      = (const float*)d_in[0];   // [64,1,784,500] fp32
    const int*   weight = (const int*)d_in[1];     // [512,784] int32 in [0,8)
    const int*   table  = (const int*)d_in[2];     // [8,21] int32 (flipped)
    float*       out    = (float*)d_out;           // [64,1,512,522] fp32

    cudaFuncSetAttribute(pot_kernel, cudaFuncAttributeMaxDynamicSharedMemorySize, SMEM_TOTAL);

    cudaMemsetAsync(out, 0, (size_t)out_size * sizeof(float), 0);
    init_kernel<<<(B_ * TP_ + 255) / 256, 256>>>();

    prepass_kernel<<<(B_ * S_ * (T_ / 4) + 255) / 256, 256>>>((const float4*)x);

    dim3 grid(N_ / NT_, B_);
    pot_kernel<<<grid, THREADS_, SMEM_TOTAL>>>(weight, table);

    scan_kernel<<<B_, 128>>>(out);
}